// round 2
// baseline (speedup 1.0000x reference)
#include <cuda_runtime.h>
#include <cstdint>

#define NS 512
#define NR 384
#define CM 256
#define CO 32
#define CZ 128
#define MTOT (NR*CO)   // 12288

// Scratch (static device allocations are allowed)
__device__ float g_left [NS * MTOT];   // [a][b*32+c]
__device__ float g_right[NS * MTOT];   // [a][d*32+e]
__device__ float g_rnorm[NR * NR];     // 1/(eps + norm[b][d])

// ---------------------------------------------------------------------------
// Kernel 1: LayerNorm + left/right projections (+mask), one block per (a,b)
// ---------------------------------------------------------------------------
__global__ __launch_bounds__(256) void ln_proj_kernel(
    const float* __restrict__ act, const float* __restrict__ mask,
    const float* __restrict__ ln_w, const float* __restrict__ ln_b,
    const float* __restrict__ lw, const float* __restrict__ lb,
    const float* __restrict__ rw, const float* __restrict__ rb)
{
    int idx = blockIdx.x;            // a*384 + b
    int a = idx / NR;
    int b = idx - a * NR;
    int t = threadIdx.x;

    __shared__ float s_act[CM];
    __shared__ float red1[8], red2[8];

    float x = act[(size_t)idx * CM + t];
    float s1 = x, s2 = x * x;
    #pragma unroll
    for (int o = 16; o; o >>= 1) {
        s1 += __shfl_xor_sync(0xffffffffu, s1, o);
        s2 += __shfl_xor_sync(0xffffffffu, s2, o);
    }
    int warp = t >> 5, lane = t & 31;
    if (lane == 0) { red1[warp] = s1; red2[warp] = s2; }
    __syncthreads();
    if (t < 32) {
        float a1 = (t < 8) ? red1[t] : 0.f;
        float a2 = (t < 8) ? red2[t] : 0.f;
        #pragma unroll
        for (int o = 4; o; o >>= 1) {
            a1 += __shfl_xor_sync(0xffffffffu, a1, o);
            a2 += __shfl_xor_sync(0xffffffffu, a2, o);
        }
        if (t == 0) { red1[0] = a1; red2[0] = a2; }
    }
    __syncthreads();
    float mu  = red1[0] * (1.f / CM);
    float var = red2[0] * (1.f / CM) - mu * mu;
    float inv = rsqrtf(var + 1e-5f);
    s_act[t] = (x - mu) * inv * ln_w[t] + ln_b[t];
    __syncthreads();

    // 64 outputs (32 left + 32 right), 4 threads per output
    int o = t >> 2;     // 0..63
    int q = t & 3;      // 0..3
    const float* w = (o < CO) ? (lw + o * CM) : (rw + (o - CO) * CM);
    const float4* sa4 = (const float4*)(s_act + q * 64);
    const float4* w4  = (const float4*)(w + q * 64);
    float acc = 0.f;
    #pragma unroll
    for (int i = 0; i < 16; i++) {
        float4 xa = sa4[i], xw = w4[i];
        acc += xa.x * xw.x + xa.y * xw.y + xa.z * xw.z + xa.w * xw.w;
    }
    acc += __shfl_xor_sync(0xffffffffu, acc, 1);
    acc += __shfl_xor_sync(0xffffffffu, acc, 2);
    if (q == 0) {
        float mv = mask[a * NR + b];
        if (o < CO) g_left [(size_t)a * MTOT + b * CO + o]        = mv * (acc + lb[o]);
        else        g_right[(size_t)a * MTOT + b * CO + (o - CO)] = mv * (acc + rb[o - CO]);
    }
}

// ---------------------------------------------------------------------------
// Kernel 2: reciprocal of mask-norm:  1/(1e-3 + sum_a mask[a,b]*mask[a,d])
// ---------------------------------------------------------------------------
__global__ void norm_kernel(const float* __restrict__ mask)
{
    int b = blockIdx.x * 16 + threadIdx.x;
    int d = blockIdx.y * 16 + threadIdx.y;
    float acc = 0.f;
    #pragma unroll 8
    for (int a = 0; a < NS; a++)
        acc += mask[a * NR + b] * mask[a * NR + d];
    g_rnorm[b * NR + d] = 1.f / (1e-3f + acc);
}

// ---------------------------------------------------------------------------
// Kernel 3: fused GEMM (128x128 tile of O = left^T @ right, K=512) +
//           epilogue contraction with output_w + bias + norm division.
//           Block covers 4 b's x 4 d's (16 residue pairs).
// ---------------------------------------------------------------------------
#define KC 16

__global__ __launch_bounds__(256) void opm_kernel(
    const float* __restrict__ wout,   // [32,32,128]
    const float* __restrict__ outb,   // [128]
    float* __restrict__ out)          // [384,384,128]
{
    __shared__ __align__(16) float sbuf[128 * 66];   // union: (As+Bs) | Osm-half
    float* As = sbuf;                 // [KC][128]
    float* Bs = sbuf + KC * 128;      // [KC][128]

    int t = threadIdx.x;
    int bi = blockIdx.x;   // b-tile (0..95)
    int bj = blockIdx.y;   // d-tile (0..95)

    // warp/lane tiling: 8 warps as 4(M) x 2(N); lanes as 4(M) x 8(N)
    int warp = t >> 5, lane = t & 31;
    int wm = warp >> 1, wn = warp & 1;
    int mrow = lane >> 3, ncol = lane & 7;
    int m0 = wm * 32 + mrow * 8;   // 8 M rows (4 packed pairs)
    int n0 = wn * 64 + ncol * 8;   // 8 N cols

    unsigned long long acc[4][8];  // packed (m0+2i, m0+2i+1) x n0+j
    #pragma unroll
    for (int i = 0; i < 4; i++)
        #pragma unroll
        for (int j = 0; j < 8; j++) acc[i][j] = 0ull;

    const float* Ag = g_left  + (size_t)bi * 128;
    const float* Bg = g_right + (size_t)bj * 128;

    for (int k0 = 0; k0 < NS; k0 += KC) {
        #pragma unroll
        for (int l = 0; l < 2; l++) {
            int idx4 = t + l * 256;
            int r = idx4 >> 5;
            int c = (idx4 & 31) << 2;
            const float4 va = *(const float4*)(Ag + (size_t)(k0 + r) * MTOT + c);
            const float4 vb = *(const float4*)(Bg + (size_t)(k0 + r) * MTOT + c);
            *(float4*)(As + r * 128 + c) = va;
            *(float4*)(Bs + r * 128 + c) = vb;
        }
        __syncthreads();
        #pragma unroll
        for (int kk = 0; kk < KC; kk++) {
            unsigned long long a2[4], bp[8];
            #pragma unroll
            for (int i = 0; i < 4; i++)
                a2[i] = *(const unsigned long long*)(As + kk * 128 + m0 + 2 * i);
            #pragma unroll
            for (int j = 0; j < 8; j++) {
                float bv = Bs[kk * 128 + n0 + j];
                asm("mov.b64 %0, {%1,%1};" : "=l"(bp[j]) : "f"(bv));
            }
            #pragma unroll
            for (int i = 0; i < 4; i++)
                #pragma unroll
                for (int j = 0; j < 8; j++)
                    asm("fma.rn.f32x2 %0, %1, %2, %0;"
                        : "+l"(acc[i][j]) : "l"(a2[i]), "l"(bp[j]));
        }
        __syncthreads();
    }

    // ---- epilogue: two N-halves (dd in {0,1} then {2,3}) through SMEM ----
    float* Osm = sbuf;   // [128][66] (padded)
    int f2 = t & 63;     // output f-pair index (f = 2*f2, 2*f2+1)
    int g  = t >> 6;     // 0..3
    int f0 = f2 * 2;
    float bias0 = outb[f0], bias1 = outb[f0 + 1];
    const float* wp = wout + f0;

    for (int h = 0; h < 2; h++) {
        __syncthreads();
        if (wn == h) {
            int nb = ncol * 8;
            #pragma unroll
            for (int i = 0; i < 4; i++)
                #pragma unroll
                for (int j = 0; j < 8; j++) {
                    float lo, hi;
                    asm("mov.b64 {%0,%1}, %2;" : "=f"(lo), "=f"(hi) : "l"(acc[i][j]));
                    Osm[(m0 + 2 * i)     * 66 + nb + j] = lo;
                    Osm[(m0 + 2 * i + 1) * 66 + nb + j] = hi;
                }
        }
        __syncthreads();

        // pairs this pass: p in 0..7  (bb = p>>1 in 0..3, ddl = p&1)
        int p0 = g, p1 = g + 4;
        int rb0 = (p0 >> 1) * 32, cb0 = (p0 & 1) * 32;
        int rb1 = (p1 >> 1) * 32, cb1 = (p1 & 1) * 32;
        unsigned long long ap0 = 0ull, ap1 = 0ull;
        for (int c = 0; c < 32; c++) {
            #pragma unroll 8
            for (int e = 0; e < 32; e++) {
                unsigned long long wv =
                    *(const unsigned long long*)(wp + (size_t)(c * 32 + e) * CZ);
                float o0 = Osm[(rb0 + c) * 66 + cb0 + e];
                float o1 = Osm[(rb1 + c) * 66 + cb1 + e];
                unsigned long long op0, op1;
                asm("mov.b64 %0, {%1,%1};" : "=l"(op0) : "f"(o0));
                asm("mov.b64 %0, {%1,%1};" : "=l"(op1) : "f"(o1));
                asm("fma.rn.f32x2 %0, %1, %2, %0;" : "+l"(ap0) : "l"(op0), "l"(wv));
                asm("fma.rn.f32x2 %0, %1, %2, %0;" : "+l"(ap1) : "l"(op1), "l"(wv));
            }
        }
        // write both pairs
        #pragma unroll
        for (int s = 0; s < 2; s++) {
            unsigned long long ap = s ? ap1 : ap0;
            int p  = s ? p1 : p0;
            int bb = p >> 1, ddl = p & 1;
            int bg = bi * 4 + bb;
            int dg = bj * 4 + h * 2 + ddl;
            float rn = g_rnorm[bg * NR + dg];
            float lo, hi;
            asm("mov.b64 {%0,%1}, %2;" : "=f"(lo), "=f"(hi) : "l"(ap));
            size_t off = ((size_t)bg * NR + dg) * CZ + f0;
            float2 res = make_float2((lo + bias0) * rn, (hi + bias1) * rn);
            *(float2*)(out + off) = res;
        }
    }
}

// ---------------------------------------------------------------------------
extern "C" void kernel_launch(void* const* d_in, const int* in_sizes, int n_in,
                              void* d_out, int out_size)
{
    (void)in_sizes; (void)n_in; (void)out_size;
    const float* act    = (const float*)d_in[0];
    const float* mask   = (const float*)d_in[1];
    const float* ln_w   = (const float*)d_in[2];
    const float* ln_b   = (const float*)d_in[3];
    const float* left_w = (const float*)d_in[4];
    const float* left_b = (const float*)d_in[5];
    const float* right_w= (const float*)d_in[6];
    const float* right_b= (const float*)d_in[7];
    const float* out_w  = (const float*)d_in[8];
    const float* out_b  = (const float*)d_in[9];
    float* out = (float*)d_out;

    ln_proj_kernel<<<NS * NR, 256>>>(act, mask, ln_w, ln_b,
                                     left_w, left_b, right_w, right_b);
    norm_kernel<<<dim3(NR / 16, NR / 16), dim3(16, 16)>>>(mask);
    opm_kernel<<<dim3(96, 96), 256>>>(out_w, out_b, out);
}

// round 3
// speedup vs baseline: 1.0488x; 1.0488x over previous
#include <cuda_runtime.h>
#include <cstdint>

#define NS 512
#define NR 384
#define CM 256
#define CO 32
#define CZ 128
#define MTOT (NR*CO)   // 12288

// Scratch (static device allocations are allowed)
__device__ float g_left [NS * MTOT];   // [a][b*32+c]
__device__ float g_right[NS * MTOT];   // [a][d*32+e]
__device__ float g_rnorm[NR * NR];     // 1/(eps + norm[b][d])

// ---------------------------------------------------------------------------
// Kernel 1: LayerNorm + left/right projections (+mask), one block per (a,b)
// ---------------------------------------------------------------------------
__global__ __launch_bounds__(256) void ln_proj_kernel(
    const float* __restrict__ act, const float* __restrict__ mask,
    const float* __restrict__ ln_w, const float* __restrict__ ln_b,
    const float* __restrict__ lw, const float* __restrict__ lb,
    const float* __restrict__ rw, const float* __restrict__ rb)
{
    int idx = blockIdx.x;            // a*384 + b
    int a = idx / NR;
    int b = idx - a * NR;
    int t = threadIdx.x;

    __shared__ float s_act[CM];
    __shared__ float red1[8], red2[8];

    float x = act[(size_t)idx * CM + t];
    float s1 = x, s2 = x * x;
    #pragma unroll
    for (int o = 16; o; o >>= 1) {
        s1 += __shfl_xor_sync(0xffffffffu, s1, o);
        s2 += __shfl_xor_sync(0xffffffffu, s2, o);
    }
    int warp = t >> 5, lane = t & 31;
    if (lane == 0) { red1[warp] = s1; red2[warp] = s2; }
    __syncthreads();
    if (t < 32) {
        float a1 = (t < 8) ? red1[t] : 0.f;
        float a2 = (t < 8) ? red2[t] : 0.f;
        #pragma unroll
        for (int o = 4; o; o >>= 1) {
            a1 += __shfl_xor_sync(0xffffffffu, a1, o);
            a2 += __shfl_xor_sync(0xffffffffu, a2, o);
        }
        if (t == 0) { red1[0] = a1; red2[0] = a2; }
    }
    __syncthreads();
    float mu  = red1[0] * (1.f / CM);
    float var = red2[0] * (1.f / CM) - mu * mu;
    float inv = rsqrtf(var + 1e-5f);
    s_act[t] = (x - mu) * inv * ln_w[t] + ln_b[t];
    __syncthreads();

    // 64 outputs (32 left + 32 right), 4 threads per output
    int o = t >> 2;     // 0..63
    int q = t & 3;      // 0..3
    const float* w = (o < CO) ? (lw + o * CM) : (rw + (o - CO) * CM);
    const float4* sa4 = (const float4*)(s_act + q * 64);
    const float4* w4  = (const float4*)(w + q * 64);
    float acc = 0.f;
    #pragma unroll
    for (int i = 0; i < 16; i++) {
        float4 xa = sa4[i], xw = w4[i];
        acc += xa.x * xw.x + xa.y * xw.y + xa.z * xw.z + xa.w * xw.w;
    }
    acc += __shfl_xor_sync(0xffffffffu, acc, 1);
    acc += __shfl_xor_sync(0xffffffffu, acc, 2);
    if (q == 0) {
        float mv = mask[a * NR + b];
        if (o < CO) g_left [(size_t)a * MTOT + b * CO + o]        = mv * (acc + lb[o]);
        else        g_right[(size_t)a * MTOT + b * CO + (o - CO)] = mv * (acc + rb[o - CO]);
    }
}

// ---------------------------------------------------------------------------
// Kernel 2: reciprocal of mask-norm:  1/(1e-3 + sum_a mask[a,b]*mask[a,d])
// ---------------------------------------------------------------------------
__global__ void norm_kernel(const float* __restrict__ mask)
{
    int b = blockIdx.x * 16 + threadIdx.x;
    int d = blockIdx.y * 16 + threadIdx.y;
    float acc = 0.f;
    #pragma unroll 8
    for (int a = 0; a < NS; a++)
        acc += mask[a * NR + b] * mask[a * NR + d];
    g_rnorm[b * NR + d] = 1.f / (1e-3f + acc);
}

// ---------------------------------------------------------------------------
// Kernel 3: fused GEMM (128x128 tile of O = left^T @ right, K=512) +
//           epilogue contraction with output_w + bias + norm division.
//           Block covers 4 b's x 4 d's (16 residue pairs).
// ---------------------------------------------------------------------------
#define KC 16

__global__ __launch_bounds__(256) void opm_kernel(
    const float* __restrict__ wout,   // [32,32,128]
    const float* __restrict__ outb,   // [128]
    float* __restrict__ out)          // [384,384,128]
{
    __shared__ __align__(16) float sbuf[128 * 66];   // union: (As+Bs) | Osm-half
    float* As = sbuf;                 // [KC][128]
    float* Bs = sbuf + KC * 128;      // [KC][128]

    int t = threadIdx.x;
    int bi = blockIdx.x;   // b-tile (0..95)
    int bj = blockIdx.y;   // d-tile (0..95)

    // warp/lane tiling: 8 warps as 4(M) x 2(N); lanes as 4(M) x 8(N)
    int warp = t >> 5, lane = t & 31;
    int wm = warp >> 1, wn = warp & 1;
    int mrow = lane >> 3, ncol = lane & 7;
    int m0 = wm * 32 + mrow * 8;   // 8 M rows (4 packed pairs)
    int n0 = wn * 64 + ncol * 8;   // 8 N cols

    unsigned long long acc[4][8];  // packed (m0+2i, m0+2i+1) x n0+j
    #pragma unroll
    for (int i = 0; i < 4; i++)
        #pragma unroll
        for (int j = 0; j < 8; j++) acc[i][j] = 0ull;

    const float* Ag = g_left  + (size_t)bi * 128;
    const float* Bg = g_right + (size_t)bj * 128;

    for (int k0 = 0; k0 < NS; k0 += KC) {
        #pragma unroll
        for (int l = 0; l < 2; l++) {
            int idx4 = t + l * 256;
            int r = idx4 >> 5;
            int c = (idx4 & 31) << 2;
            const float4 va = *(const float4*)(Ag + (size_t)(k0 + r) * MTOT + c);
            const float4 vb = *(const float4*)(Bg + (size_t)(k0 + r) * MTOT + c);
            *(float4*)(As + r * 128 + c) = va;
            *(float4*)(Bs + r * 128 + c) = vb;
        }
        __syncthreads();
        #pragma unroll
        for (int kk = 0; kk < KC; kk++) {
            unsigned long long a2[4], bp[8];
            #pragma unroll
            for (int i = 0; i < 4; i++)
                a2[i] = *(const unsigned long long*)(As + kk * 128 + m0 + 2 * i);
            #pragma unroll
            for (int j = 0; j < 8; j++) {
                float bv = Bs[kk * 128 + n0 + j];
                asm("mov.b64 %0, {%1,%1};" : "=l"(bp[j]) : "f"(bv));
            }
            #pragma unroll
            for (int i = 0; i < 4; i++)
                #pragma unroll
                for (int j = 0; j < 8; j++)
                    asm("fma.rn.f32x2 %0, %1, %2, %0;"
                        : "+l"(acc[i][j]) : "l"(a2[i]), "l"(bp[j]));
        }
        __syncthreads();
    }

    // ---- epilogue: two N-halves (dd in {0,1} then {2,3}) through SMEM ----
    float* Osm = sbuf;   // [128][66] (padded)
    int f2 = t & 63;     // output f-pair index (f = 2*f2, 2*f2+1)
    int g  = t >> 6;     // 0..3
    int f0 = f2 * 2;
    float bias0 = outb[f0], bias1 = outb[f0 + 1];
    const float* wp = wout + f0;

    for (int h = 0; h < 2; h++) {
        __syncthreads();
        if (wn == h) {
            int nb = ncol * 8;
            #pragma unroll
            for (int i = 0; i < 4; i++)
                #pragma unroll
                for (int j = 0; j < 8; j++) {
                    float lo, hi;
                    asm("mov.b64 {%0,%1}, %2;" : "=f"(lo), "=f"(hi) : "l"(acc[i][j]));
                    Osm[(m0 + 2 * i)     * 66 + nb + j] = lo;
                    Osm[(m0 + 2 * i + 1) * 66 + nb + j] = hi;
                }
        }
        __syncthreads();

        // pairs this pass: p in 0..7  (bb = p>>1 in 0..3, ddl = p&1)
        int p0 = g, p1 = g + 4;
        int rb0 = (p0 >> 1) * 32, cb0 = (p0 & 1) * 32;
        int rb1 = (p1 >> 1) * 32, cb1 = (p1 & 1) * 32;
        unsigned long long ap0 = 0ull, ap1 = 0ull;
        for (int c = 0; c < 32; c++) {
            #pragma unroll 8
            for (int e = 0; e < 32; e++) {
                unsigned long long wv =
                    *(const unsigned long long*)(wp + (size_t)(c * 32 + e) * CZ);
                float o0 = Osm[(rb0 + c) * 66 + cb0 + e];
                float o1 = Osm[(rb1 + c) * 66 + cb1 + e];
                unsigned long long op0, op1;
                asm("mov.b64 %0, {%1,%1};" : "=l"(op0) : "f"(o0));
                asm("mov.b64 %0, {%1,%1};" : "=l"(op1) : "f"(o1));
                asm("fma.rn.f32x2 %0, %1, %2, %0;" : "+l"(ap0) : "l"(op0), "l"(wv));
                asm("fma.rn.f32x2 %0, %1, %2, %0;" : "+l"(ap1) : "l"(op1), "l"(wv));
            }
        }
        // write both pairs
        #pragma unroll
        for (int s = 0; s < 2; s++) {
            unsigned long long ap = s ? ap1 : ap0;
            int p  = s ? p1 : p0;
            int bb = p >> 1, ddl = p & 1;
            int bg = bi * 4 + bb;
            int dg = bj * 4 + h * 2 + ddl;
            float rn = g_rnorm[bg * NR + dg];
            float lo, hi;
            asm("mov.b64 {%0,%1}, %2;" : "=f"(lo), "=f"(hi) : "l"(ap));
            size_t off = ((size_t)bg * NR + dg) * CZ + f0;
            float2 res = make_float2((lo + bias0) * rn, (hi + bias1) * rn);
            *(float2*)(out + off) = res;
        }
    }
}

// ---------------------------------------------------------------------------
extern "C" void kernel_launch(void* const* d_in, const int* in_sizes, int n_in,
                              void* d_out, int out_size)
{
    (void)in_sizes; (void)n_in; (void)out_size;
    const float* act    = (const float*)d_in[0];
    const float* mask   = (const float*)d_in[1];
    const float* ln_w   = (const float*)d_in[2];
    const float* ln_b   = (const float*)d_in[3];
    const float* left_w = (const float*)d_in[4];
    const float* left_b = (const float*)d_in[5];
    const float* right_w= (const float*)d_in[6];
    const float* right_b= (const float*)d_in[7];
    const float* out_w  = (const float*)d_in[8];
    const float* out_b  = (const float*)d_in[9];
    float* out = (float*)d_out;

    ln_proj_kernel<<<NS * NR, 256>>>(act, mask, ln_w, ln_b,
                                     left_w, left_b, right_w, right_b);
    norm_kernel<<<dim3(NR / 16, NR / 16), dim3(16, 16)>>>(mask);
    opm_kernel<<<dim3(96, 96), 256>>>(out_w, out_b, out);
}

// round 4
// speedup vs baseline: 1.0489x; 1.0000x over previous
#include <cuda_runtime.h>
#include <cstdint>

#define NS 512
#define NR 384
#define CM 256
#define CO 32
#define CZ 128
#define MTOT (NR*CO)   // 12288

// Scratch (static device allocations are allowed)
__device__ float g_left [NS * MTOT];   // [a][b*32+c]
__device__ float g_right[NS * MTOT];   // [a][d*32+e]
__device__ float g_rnorm[NR * NR];     // 1/(eps + norm[b][d])

// ---------------------------------------------------------------------------
// Kernel 1: LayerNorm + left/right projections (+mask), one block per (a,b)
// ---------------------------------------------------------------------------
__global__ __launch_bounds__(256) void ln_proj_kernel(
    const float* __restrict__ act, const float* __restrict__ mask,
    const float* __restrict__ ln_w, const float* __restrict__ ln_b,
    const float* __restrict__ lw, const float* __restrict__ lb,
    const float* __restrict__ rw, const float* __restrict__ rb)
{
    int idx = blockIdx.x;            // a*384 + b
    int a = idx / NR;
    int b = idx - a * NR;
    int t = threadIdx.x;

    __shared__ float s_act[CM];
    __shared__ float red1[8], red2[8];

    float x = act[(size_t)idx * CM + t];
    float s1 = x, s2 = x * x;
    #pragma unroll
    for (int o = 16; o; o >>= 1) {
        s1 += __shfl_xor_sync(0xffffffffu, s1, o);
        s2 += __shfl_xor_sync(0xffffffffu, s2, o);
    }
    int warp = t >> 5, lane = t & 31;
    if (lane == 0) { red1[warp] = s1; red2[warp] = s2; }
    __syncthreads();
    if (t < 32) {
        float a1 = (t < 8) ? red1[t] : 0.f;
        float a2 = (t < 8) ? red2[t] : 0.f;
        #pragma unroll
        for (int o = 4; o; o >>= 1) {
            a1 += __shfl_xor_sync(0xffffffffu, a1, o);
            a2 += __shfl_xor_sync(0xffffffffu, a2, o);
        }
        if (t == 0) { red1[0] = a1; red2[0] = a2; }
    }
    __syncthreads();
    float mu  = red1[0] * (1.f / CM);
    float var = red2[0] * (1.f / CM) - mu * mu;
    float inv = rsqrtf(var + 1e-5f);
    s_act[t] = (x - mu) * inv * ln_w[t] + ln_b[t];
    __syncthreads();

    // 64 outputs (32 left + 32 right), 4 threads per output
    int o = t >> 2;     // 0..63
    int q = t & 3;      // 0..3
    const float* w = (o < CO) ? (lw + o * CM) : (rw + (o - CO) * CM);
    const float4* sa4 = (const float4*)(s_act + q * 64);
    const float4* w4  = (const float4*)(w + q * 64);
    float acc = 0.f;
    #pragma unroll
    for (int i = 0; i < 16; i++) {
        float4 xa = sa4[i], xw = w4[i];
        acc += xa.x * xw.x + xa.y * xw.y + xa.z * xw.z + xa.w * xw.w;
    }
    acc += __shfl_xor_sync(0xffffffffu, acc, 1);
    acc += __shfl_xor_sync(0xffffffffu, acc, 2);
    if (q == 0) {
        float mv = mask[a * NR + b];
        if (o < CO) g_left [(size_t)a * MTOT + b * CO + o]        = mv * (acc + lb[o]);
        else        g_right[(size_t)a * MTOT + b * CO + (o - CO)] = mv * (acc + rb[o - CO]);
    }
}

// ---------------------------------------------------------------------------
// Kernel 2: reciprocal of mask-norm:  1/(1e-3 + sum_a mask[a,b]*mask[a,d])
// ---------------------------------------------------------------------------
__global__ void norm_kernel(const float* __restrict__ mask)
{
    int b = blockIdx.x * 16 + threadIdx.x;
    int d = blockIdx.y * 16 + threadIdx.y;
    float acc = 0.f;
    #pragma unroll 8
    for (int a = 0; a < NS; a++)
        acc += mask[a * NR + b] * mask[a * NR + d];
    g_rnorm[b * NR + d] = 1.f / (1e-3f + acc);
}

// ---------------------------------------------------------------------------
// Kernel 3: fused GEMM (128x128 tile of O = left^T @ right, K=512) +
//           epilogue contraction with output_w + bias + norm division.
//           Block covers 4 b's x 4 d's (16 residue pairs).
// ---------------------------------------------------------------------------
#define KC 16

__global__ __launch_bounds__(256) void opm_kernel(
    const float* __restrict__ wout,   // [32,32,128]
    const float* __restrict__ outb,   // [128]
    float* __restrict__ out)          // [384,384,128]
{
    __shared__ __align__(16) float sbuf[128 * 66];   // union: (As+Bs) | Osm-half
    float* As = sbuf;                 // [KC][128]
    float* Bs = sbuf + KC * 128;      // [KC][128]

    int t = threadIdx.x;
    int bi = blockIdx.x;   // b-tile (0..95)
    int bj = blockIdx.y;   // d-tile (0..95)

    // warp/lane tiling: 8 warps as 4(M) x 2(N); lanes as 4(M) x 8(N)
    int warp = t >> 5, lane = t & 31;
    int wm = warp >> 1, wn = warp & 1;
    int mrow = lane >> 3, ncol = lane & 7;
    int m0 = wm * 32 + mrow * 8;   // 8 M rows (4 packed pairs)
    int n0 = wn * 64 + ncol * 8;   // 8 N cols

    unsigned long long acc[4][8];  // packed (m0+2i, m0+2i+1) x n0+j
    #pragma unroll
    for (int i = 0; i < 4; i++)
        #pragma unroll
        for (int j = 0; j < 8; j++) acc[i][j] = 0ull;

    const float* Ag = g_left  + (size_t)bi * 128;
    const float* Bg = g_right + (size_t)bj * 128;

    for (int k0 = 0; k0 < NS; k0 += KC) {
        #pragma unroll
        for (int l = 0; l < 2; l++) {
            int idx4 = t + l * 256;
            int r = idx4 >> 5;
            int c = (idx4 & 31) << 2;
            const float4 va = *(const float4*)(Ag + (size_t)(k0 + r) * MTOT + c);
            const float4 vb = *(const float4*)(Bg + (size_t)(k0 + r) * MTOT + c);
            *(float4*)(As + r * 128 + c) = va;
            *(float4*)(Bs + r * 128 + c) = vb;
        }
        __syncthreads();
        #pragma unroll
        for (int kk = 0; kk < KC; kk++) {
            unsigned long long a2[4], bp[8];
            #pragma unroll
            for (int i = 0; i < 4; i++)
                a2[i] = *(const unsigned long long*)(As + kk * 128 + m0 + 2 * i);
            #pragma unroll
            for (int j = 0; j < 8; j++) {
                float bv = Bs[kk * 128 + n0 + j];
                asm("mov.b64 %0, {%1,%1};" : "=l"(bp[j]) : "f"(bv));
            }
            #pragma unroll
            for (int i = 0; i < 4; i++)
                #pragma unroll
                for (int j = 0; j < 8; j++)
                    asm("fma.rn.f32x2 %0, %1, %2, %0;"
                        : "+l"(acc[i][j]) : "l"(a2[i]), "l"(bp[j]));
        }
        __syncthreads();
    }

    // ---- epilogue: two N-halves (dd in {0,1} then {2,3}) through SMEM ----
    float* Osm = sbuf;   // [128][66] (padded)
    int f2 = t & 63;     // output f-pair index (f = 2*f2, 2*f2+1)
    int g  = t >> 6;     // 0..3
    int f0 = f2 * 2;
    float bias0 = outb[f0], bias1 = outb[f0 + 1];
    const float* wp = wout + f0;

    for (int h = 0; h < 2; h++) {
        __syncthreads();
        if (wn == h) {
            int nb = ncol * 8;
            #pragma unroll
            for (int i = 0; i < 4; i++)
                #pragma unroll
                for (int j = 0; j < 8; j++) {
                    float lo, hi;
                    asm("mov.b64 {%0,%1}, %2;" : "=f"(lo), "=f"(hi) : "l"(acc[i][j]));
                    Osm[(m0 + 2 * i)     * 66 + nb + j] = lo;
                    Osm[(m0 + 2 * i + 1) * 66 + nb + j] = hi;
                }
        }
        __syncthreads();

        // pairs this pass: p in 0..7  (bb = p>>1 in 0..3, ddl = p&1)
        int p0 = g, p1 = g + 4;
        int rb0 = (p0 >> 1) * 32, cb0 = (p0 & 1) * 32;
        int rb1 = (p1 >> 1) * 32, cb1 = (p1 & 1) * 32;
        unsigned long long ap0 = 0ull, ap1 = 0ull;
        for (int c = 0; c < 32; c++) {
            #pragma unroll 8
            for (int e = 0; e < 32; e++) {
                unsigned long long wv =
                    *(const unsigned long long*)(wp + (size_t)(c * 32 + e) * CZ);
                float o0 = Osm[(rb0 + c) * 66 + cb0 + e];
                float o1 = Osm[(rb1 + c) * 66 + cb1 + e];
                unsigned long long op0, op1;
                asm("mov.b64 %0, {%1,%1};" : "=l"(op0) : "f"(o0));
                asm("mov.b64 %0, {%1,%1};" : "=l"(op1) : "f"(o1));
                asm("fma.rn.f32x2 %0, %1, %2, %0;" : "+l"(ap0) : "l"(op0), "l"(wv));
                asm("fma.rn.f32x2 %0, %1, %2, %0;" : "+l"(ap1) : "l"(op1), "l"(wv));
            }
        }
        // write both pairs
        #pragma unroll
        for (int s = 0; s < 2; s++) {
            unsigned long long ap = s ? ap1 : ap0;
            int p  = s ? p1 : p0;
            int bb = p >> 1, ddl = p & 1;
            int bg = bi * 4 + bb;
            int dg = bj * 4 + h * 2 + ddl;
            float rn = g_rnorm[bg * NR + dg];
            float lo, hi;
            asm("mov.b64 {%0,%1}, %2;" : "=f"(lo), "=f"(hi) : "l"(ap));
            size_t off = ((size_t)bg * NR + dg) * CZ + f0;
            float2 res = make_float2((lo + bias0) * rn, (hi + bias1) * rn);
            *(float2*)(out + off) = res;
        }
    }
}

// ---------------------------------------------------------------------------
extern "C" void kernel_launch(void* const* d_in, const int* in_sizes, int n_in,
                              void* d_out, int out_size)
{
    (void)in_sizes; (void)n_in; (void)out_size;
    const float* act    = (const float*)d_in[0];
    const float* mask   = (const float*)d_in[1];
    const float* ln_w   = (const float*)d_in[2];
    const float* ln_b   = (const float*)d_in[3];
    const float* left_w = (const float*)d_in[4];
    const float* left_b = (const float*)d_in[5];
    const float* right_w= (const float*)d_in[6];
    const float* right_b= (const float*)d_in[7];
    const float* out_w  = (const float*)d_in[8];
    const float* out_b  = (const float*)d_in[9];
    float* out = (float*)d_out;

    ln_proj_kernel<<<NS * NR, 256>>>(act, mask, ln_w, ln_b,
                                     left_w, left_b, right_w, right_b);
    norm_kernel<<<dim3(NR / 16, NR / 16), dim3(16, 16)>>>(mask);
    opm_kernel<<<dim3(96, 96), 256>>>(out_w, out_b, out);
}

// round 5
// speedup vs baseline: 1.0504x; 1.0014x over previous
#include <cuda_runtime.h>
#include <cstdint>

#define NS 512
#define NR 384
#define CM 256
#define CO 32
#define CZ 128
#define MTOT (NR*CO)   // 12288

// Scratch (static device allocations are allowed)
__device__ float g_left [NS * MTOT];   // [a][b*32+c]
__device__ float g_right[NS * MTOT];   // [a][d*32+e]
__device__ float g_rnorm[NR * NR];     // 1/(eps + norm[b][d])

// ---------------------------------------------------------------------------
// Kernel 1: LayerNorm + left/right projections (+mask), one block per (a,b)
// ---------------------------------------------------------------------------
__global__ __launch_bounds__(256) void ln_proj_kernel(
    const float* __restrict__ act, const float* __restrict__ mask,
    const float* __restrict__ ln_w, const float* __restrict__ ln_b,
    const float* __restrict__ lw, const float* __restrict__ lb,
    const float* __restrict__ rw, const float* __restrict__ rb)
{
    int idx = blockIdx.x;            // a*384 + b
    int a = idx / NR;
    int b = idx - a * NR;
    int t = threadIdx.x;

    __shared__ float s_act[CM];
    __shared__ float red1[8], red2[8];

    float x = act[(size_t)idx * CM + t];
    float s1 = x, s2 = x * x;
    #pragma unroll
    for (int o = 16; o; o >>= 1) {
        s1 += __shfl_xor_sync(0xffffffffu, s1, o);
        s2 += __shfl_xor_sync(0xffffffffu, s2, o);
    }
    int warp = t >> 5, lane = t & 31;
    if (lane == 0) { red1[warp] = s1; red2[warp] = s2; }
    __syncthreads();
    if (t < 32) {
        float a1 = (t < 8) ? red1[t] : 0.f;
        float a2 = (t < 8) ? red2[t] : 0.f;
        #pragma unroll
        for (int o = 4; o; o >>= 1) {
            a1 += __shfl_xor_sync(0xffffffffu, a1, o);
            a2 += __shfl_xor_sync(0xffffffffu, a2, o);
        }
        if (t == 0) { red1[0] = a1; red2[0] = a2; }
    }
    __syncthreads();
    float mu  = red1[0] * (1.f / CM);
    float var = red2[0] * (1.f / CM) - mu * mu;
    float inv = rsqrtf(var + 1e-5f);
    s_act[t] = (x - mu) * inv * ln_w[t] + ln_b[t];
    __syncthreads();

    // 64 outputs (32 left + 32 right), 4 threads per output
    int o = t >> 2;     // 0..63
    int q = t & 3;      // 0..3
    const float* w = (o < CO) ? (lw + o * CM) : (rw + (o - CO) * CM);
    const float4* sa4 = (const float4*)(s_act + q * 64);
    const float4* w4  = (const float4*)(w + q * 64);
    float acc = 0.f;
    #pragma unroll
    for (int i = 0; i < 16; i++) {
        float4 xa = sa4[i], xw = w4[i];
        acc += xa.x * xw.x + xa.y * xw.y + xa.z * xw.z + xa.w * xw.w;
    }
    acc += __shfl_xor_sync(0xffffffffu, acc, 1);
    acc += __shfl_xor_sync(0xffffffffu, acc, 2);
    if (q == 0) {
        float mv = mask[a * NR + b];
        if (o < CO) g_left [(size_t)a * MTOT + b * CO + o]        = mv * (acc + lb[o]);
        else        g_right[(size_t)a * MTOT + b * CO + (o - CO)] = mv * (acc + rb[o - CO]);
    }
}

// ---------------------------------------------------------------------------
// Kernel 2: reciprocal of mask-norm:  1/(1e-3 + sum_a mask[a,b]*mask[a,d])
// ---------------------------------------------------------------------------
__global__ void norm_kernel(const float* __restrict__ mask)
{
    int b = blockIdx.x * 16 + threadIdx.x;
    int d = blockIdx.y * 16 + threadIdx.y;
    float acc = 0.f;
    #pragma unroll 8
    for (int a = 0; a < NS; a++)
        acc += mask[a * NR + b] * mask[a * NR + d];
    g_rnorm[b * NR + d] = 1.f / (1e-3f + acc);
}

// ---------------------------------------------------------------------------
// Kernel 3: fused GEMM (128x128 tile of O = left^T @ right, K=512) +
//           epilogue contraction with output_w + bias + norm division.
//           Block covers 4 b's x 4 d's (16 residue pairs).
// ---------------------------------------------------------------------------
#define KC 16

__global__ __launch_bounds__(256) void opm_kernel(
    const float* __restrict__ wout,   // [32,32,128]
    const float* __restrict__ outb,   // [128]
    float* __restrict__ out)          // [384,384,128]
{
    __shared__ __align__(16) float sbuf[128 * 66];   // union: (As+Bs) | Osm-half
    float* As = sbuf;                 // [KC][128]
    float* Bs = sbuf + KC * 128;      // [KC][128]

    int t = threadIdx.x;
    int bi = blockIdx.x;   // b-tile (0..95)
    int bj = blockIdx.y;   // d-tile (0..95)

    // warp/lane tiling: 8 warps as 4(M) x 2(N); lanes as 4(M) x 8(N)
    int warp = t >> 5, lane = t & 31;
    int wm = warp >> 1, wn = warp & 1;
    int mrow = lane >> 3, ncol = lane & 7;
    int m0 = wm * 32 + mrow * 8;   // 8 M rows (4 packed pairs)
    int n0 = wn * 64 + ncol * 8;   // 8 N cols

    unsigned long long acc[4][8];  // packed (m0+2i, m0+2i+1) x n0+j
    #pragma unroll
    for (int i = 0; i < 4; i++)
        #pragma unroll
        for (int j = 0; j < 8; j++) acc[i][j] = 0ull;

    const float* Ag = g_left  + (size_t)bi * 128;
    const float* Bg = g_right + (size_t)bj * 128;

    for (int k0 = 0; k0 < NS; k0 += KC) {
        #pragma unroll
        for (int l = 0; l < 2; l++) {
            int idx4 = t + l * 256;
            int r = idx4 >> 5;
            int c = (idx4 & 31) << 2;
            const float4 va = *(const float4*)(Ag + (size_t)(k0 + r) * MTOT + c);
            const float4 vb = *(const float4*)(Bg + (size_t)(k0 + r) * MTOT + c);
            *(float4*)(As + r * 128 + c) = va;
            *(float4*)(Bs + r * 128 + c) = vb;
        }
        __syncthreads();
        #pragma unroll
        for (int kk = 0; kk < KC; kk++) {
            unsigned long long a2[4], bp[8];
            #pragma unroll
            for (int i = 0; i < 4; i++)
                a2[i] = *(const unsigned long long*)(As + kk * 128 + m0 + 2 * i);
            #pragma unroll
            for (int j = 0; j < 8; j++) {
                float bv = Bs[kk * 128 + n0 + j];
                asm("mov.b64 %0, {%1,%1};" : "=l"(bp[j]) : "f"(bv));
            }
            #pragma unroll
            for (int i = 0; i < 4; i++)
                #pragma unroll
                for (int j = 0; j < 8; j++)
                    asm("fma.rn.f32x2 %0, %1, %2, %0;"
                        : "+l"(acc[i][j]) : "l"(a2[i]), "l"(bp[j]));
        }
        __syncthreads();
    }

    // ---- epilogue: two N-halves (dd in {0,1} then {2,3}) through SMEM ----
    float* Osm = sbuf;   // [128][66] (padded)
    int f2 = t & 63;     // output f-pair index (f = 2*f2, 2*f2+1)
    int g  = t >> 6;     // 0..3
    int f0 = f2 * 2;
    float bias0 = outb[f0], bias1 = outb[f0 + 1];
    const float* wp = wout + f0;

    for (int h = 0; h < 2; h++) {
        __syncthreads();
        if (wn == h) {
            int nb = ncol * 8;
            #pragma unroll
            for (int i = 0; i < 4; i++)
                #pragma unroll
                for (int j = 0; j < 8; j++) {
                    float lo, hi;
                    asm("mov.b64 {%0,%1}, %2;" : "=f"(lo), "=f"(hi) : "l"(acc[i][j]));
                    Osm[(m0 + 2 * i)     * 66 + nb + j] = lo;
                    Osm[(m0 + 2 * i + 1) * 66 + nb + j] = hi;
                }
        }
        __syncthreads();

        // pairs this pass: p in 0..7  (bb = p>>1 in 0..3, ddl = p&1)
        int p0 = g, p1 = g + 4;
        int rb0 = (p0 >> 1) * 32, cb0 = (p0 & 1) * 32;
        int rb1 = (p1 >> 1) * 32, cb1 = (p1 & 1) * 32;
        unsigned long long ap0 = 0ull, ap1 = 0ull;
        for (int c = 0; c < 32; c++) {
            #pragma unroll 8
            for (int e = 0; e < 32; e++) {
                unsigned long long wv =
                    *(const unsigned long long*)(wp + (size_t)(c * 32 + e) * CZ);
                float o0 = Osm[(rb0 + c) * 66 + cb0 + e];
                float o1 = Osm[(rb1 + c) * 66 + cb1 + e];
                unsigned long long op0, op1;
                asm("mov.b64 %0, {%1,%1};" : "=l"(op0) : "f"(o0));
                asm("mov.b64 %0, {%1,%1};" : "=l"(op1) : "f"(o1));
                asm("fma.rn.f32x2 %0, %1, %2, %0;" : "+l"(ap0) : "l"(op0), "l"(wv));
                asm("fma.rn.f32x2 %0, %1, %2, %0;" : "+l"(ap1) : "l"(op1), "l"(wv));
            }
        }
        // write both pairs
        #pragma unroll
        for (int s = 0; s < 2; s++) {
            unsigned long long ap = s ? ap1 : ap0;
            int p  = s ? p1 : p0;
            int bb = p >> 1, ddl = p & 1;
            int bg = bi * 4 + bb;
            int dg = bj * 4 + h * 2 + ddl;
            float rn = g_rnorm[bg * NR + dg];
            float lo, hi;
            asm("mov.b64 {%0,%1}, %2;" : "=f"(lo), "=f"(hi) : "l"(ap));
            size_t off = ((size_t)bg * NR + dg) * CZ + f0;
            float2 res = make_float2((lo + bias0) * rn, (hi + bias1) * rn);
            *(float2*)(out + off) = res;
        }
    }
}

// ---------------------------------------------------------------------------
extern "C" void kernel_launch(void* const* d_in, const int* in_sizes, int n_in,
                              void* d_out, int out_size)
{
    (void)in_sizes; (void)n_in; (void)out_size;
    const float* act    = (const float*)d_in[0];
    const float* mask   = (const float*)d_in[1];
    const float* ln_w   = (const float*)d_in[2];
    const float* ln_b   = (const float*)d_in[3];
    const float* left_w = (const float*)d_in[4];
    const float* left_b = (const float*)d_in[5];
    const float* right_w= (const float*)d_in[6];
    const float* right_b= (const float*)d_in[7];
    const float* out_w  = (const float*)d_in[8];
    const float* out_b  = (const float*)d_in[9];
    float* out = (float*)d_out;

    ln_proj_kernel<<<NS * NR, 256>>>(act, mask, ln_w, ln_b,
                                     left_w, left_b, right_w, right_b);
    norm_kernel<<<dim3(NR / 16, NR / 16), dim3(16, 16)>>>(mask);
    opm_kernel<<<dim3(96, 96), 256>>>(out_w, out_b, out);
}